// round 5
// baseline (speedup 1.0000x reference)
#include <cuda_runtime.h>
#include <cuda_bf16.h>
#include <cstdint>

// ---------------------------------------------------------------------------
// GraphSAGE 3-layer. Transform-then-aggregate + CSR gather with fused epilogue.
//   out = maybe_relu( csr_mean_gather(X@Wl) + X@Wr + b )
// GEMM uses packed f32x2 FFMA2 (2 output rows per 64-bit lane) -> 2x fp32 rate.
// ---------------------------------------------------------------------------

#define N_NODES 100000
#define N_EDGES 1600000

__device__ float g_yl[(size_t)N_NODES * 128];
__device__ float g_yr[(size_t)N_NODES * 128];
__device__ float g_bufA[(size_t)N_NODES * 128];
__device__ float g_bufB[(size_t)N_NODES * 128];
__device__ int   g_cnt[N_NODES];
__device__ int   g_off[N_NODES];
__device__ int   g_cur[N_NODES];
__device__ int   g_csr[N_EDGES];
__device__ int   g_bsum[128];
__device__ int   g_is64;

// --------------------------- edge dtype probe ------------------------------
__global__ void detect_kernel(const void* ei) {
    const long long* e64 = (const long long*)ei;
    int is64 = 1;
    for (int i = 0; i < 64; i++) {
        long long v = e64[i];
        if (v < 0 || v >= N_NODES) { is64 = 0; break; }
    }
    g_is64 = is64;
}

__device__ __forceinline__ int load_idx(const void* ei, long long pos) {
    if (g_is64) return (int)((const long long*)ei)[pos];
    return ((const int*)ei)[pos];
}

// ------------------------------- CSR build ---------------------------------
__global__ void zero_int_kernel(int* __restrict__ p, int n) {
    int i = blockIdx.x * blockDim.x + threadIdx.x;
    if (i < n) p[i] = 0;
}

__global__ void hist_kernel(const void* __restrict__ ei, int* __restrict__ cnt) {
    int e = blockIdx.x * blockDim.x + threadIdx.x;
    if (e < N_EDGES) {
        int d = load_idx(ei, (long long)N_EDGES + e);
        if ((unsigned)d < N_NODES) atomicAdd(&cnt[d], 1);
    }
}

__global__ void blockreduce_kernel(const int* __restrict__ cnt, int* __restrict__ bsum) {
    __shared__ int sm[256];
    int b = blockIdx.x, t = threadIdx.x;
    int base = b * 1024 + t * 4;
    int s = 0;
    #pragma unroll
    for (int i = 0; i < 4; i++) {
        int idx = base + i;
        if (idx < N_NODES) s += cnt[idx];
    }
    sm[t] = s; __syncthreads();
    for (int st = 128; st > 0; st >>= 1) {
        if (t < st) sm[t] += sm[t + st];
        __syncthreads();
    }
    if (t == 0) bsum[b] = sm[0];
}

__global__ void scanpart_kernel(int* __restrict__ bsum, int nb) {
    if (threadIdx.x == 0) {
        int acc = 0;
        for (int i = 0; i < nb; i++) { int v = bsum[i]; bsum[i] = acc; acc += v; }
    }
}

__global__ void scanfinal_kernel(const int* __restrict__ cnt, const int* __restrict__ bsum,
                                 int* __restrict__ off, int* __restrict__ cur) {
    __shared__ int sm[256];
    int b = blockIdx.x, t = threadIdx.x;
    int base = b * 1024 + t * 4;
    int v[4]; int s = 0;
    #pragma unroll
    for (int i = 0; i < 4; i++) {
        int idx = base + i;
        v[i] = (idx < N_NODES) ? cnt[idx] : 0;
        s += v[i];
    }
    sm[t] = s; __syncthreads();
    for (int st = 1; st < 256; st <<= 1) {
        int x = (t >= st) ? sm[t - st] : 0;
        __syncthreads();
        sm[t] += x;
        __syncthreads();
    }
    int run = sm[t] - s + bsum[b];
    #pragma unroll
    for (int i = 0; i < 4; i++) {
        int idx = base + i;
        if (idx < N_NODES) { off[idx] = run; cur[idx] = run; }
        run += v[i];
    }
}

__global__ void fill_kernel(const void* __restrict__ ei, int* __restrict__ cur,
                            int* __restrict__ csr) {
    int e = blockIdx.x * blockDim.x + threadIdx.x;
    if (e < N_EDGES) {
        int s = load_idx(ei, e);
        int d = load_idx(ei, (long long)N_EDGES + e);
        if ((unsigned)s < N_NODES && (unsigned)d < N_NODES) {
            int p = atomicAdd(&cur[d], 1);
            csr[p] = s;
        }
    }
}

// ---------------------------------------------------------------------------
// Packed f32x2 helpers (FFMA2 path — only reachable via PTX)
// ---------------------------------------------------------------------------
typedef unsigned long long u64;

__device__ __forceinline__ u64 pack2(float lo, float hi) {
    u64 r;
    asm("mov.b64 %0, {%1, %2};" : "=l"(r) : "f"(lo), "f"(hi));
    return r;
}
__device__ __forceinline__ u64 dup2(float v) {
    u64 r;
    asm("mov.b64 %0, {%1, %1};" : "=l"(r) : "f"(v));
    return r;
}
__device__ __forceinline__ void unpack2(u64 v, float& lo, float& hi) {
    asm("mov.b64 {%0, %1}, %2;" : "=f"(lo), "=f"(hi) : "l"(v));
}
__device__ __forceinline__ void ffma2(u64& d, u64 a, u64 b) {
    asm("fma.rn.f32x2 %0, %1, %2, %0;" : "+l"(d) : "l"(a), "l"(b));
}
__device__ __forceinline__ float comp4(const float4& v, int k) {
    switch (k) { case 0: return v.x; case 1: return v.y; case 2: return v.z; default: return v.w; }
}

// ---------------------------------------------------------------------------
// Dual GEMM (FFMA2): Yl = X@Wl, Yr = X@Wr  (X: [N,128], W: [128,DOUT])
// 64 rows x DOUT cols per 256-thread block. Each 64-bit lane carries two
// adjacent output ROWS; weights are duplicated into both halves.
// ---------------------------------------------------------------------------
template <int DOUT>
__global__ __launch_bounds__(256) void gemm_dual_kernel(
    const float* __restrict__ X,
    const float* __restrict__ Wl, const float* __restrict__ Wr,
    float* __restrict__ Yl, float* __restrict__ Yr)
{
    constexpr int TR = 64;
    __shared__ float4 sx[TR][33];   // padded row stride

    const int row0 = blockIdx.x * TR;
    const int t = threadIdx.x;

    #pragma unroll
    for (int i = t; i < TR * 32; i += 256) {
        int r = i >> 5, c4 = i & 31;
        int gr = row0 + r;
        float4 v = make_float4(0.f, 0.f, 0.f, 0.f);
        if (gr < N_NODES)
            v = reinterpret_cast<const float4*>(X + (size_t)gr * 128)[c4];
        sx[r][c4] = v;
    }
    __syncthreads();

    constexpr int CG  = DOUT / 4;     // col groups of 4
    constexpr int NG  = 256 / CG;     // row groups
    constexpr int RPT = TR / NG;      // rows per thread (8 or 4)
    constexpr int RP  = RPT / 2;      // row pairs (4 or 2)
    const int cg = t % CG;
    const int rg = t / CG;
    const int c0 = cg * 4;
    const int r0 = rg * RPT;

    u64 accl[RP][4], accr[RP][4];
    #pragma unroll
    for (int rp = 0; rp < RP; rp++)
        #pragma unroll
        for (int c = 0; c < 4; c++) { accl[rp][c] = 0ULL; accr[rp][c] = 0ULL; }

    const float4* __restrict__ Wl4 = reinterpret_cast<const float4*>(Wl + c0);
    const float4* __restrict__ Wr4 = reinterpret_cast<const float4*>(Wr + c0);

    for (int kq = 0; kq < 32; kq++) {
        float4 xa[RP], xb[RP];
        #pragma unroll
        for (int rp = 0; rp < RP; rp++) {
            xa[rp] = sx[r0 + 2 * rp + 0][kq];
            xb[rp] = sx[r0 + 2 * rp + 1][kq];
        }
        #pragma unroll
        for (int k = 0; k < 4; k++) {
            float4 wlv = Wl4[(kq * 4 + k) * CG];
            float4 wrv = Wr4[(kq * 4 + k) * CG];
            u64 l0 = dup2(wlv.x), l1 = dup2(wlv.y), l2 = dup2(wlv.z), l3 = dup2(wlv.w);
            u64 m0 = dup2(wrv.x), m1 = dup2(wrv.y), m2 = dup2(wrv.z), m3 = dup2(wrv.w);
            #pragma unroll
            for (int rp = 0; rp < RP; rp++) {
                u64 xx = pack2(comp4(xa[rp], k), comp4(xb[rp], k));
                ffma2(accl[rp][0], xx, l0);
                ffma2(accl[rp][1], xx, l1);
                ffma2(accl[rp][2], xx, l2);
                ffma2(accl[rp][3], xx, l3);
                ffma2(accr[rp][0], xx, m0);
                ffma2(accr[rp][1], xx, m1);
                ffma2(accr[rp][2], xx, m2);
                ffma2(accr[rp][3], xx, m3);
            }
        }
    }

    #pragma unroll
    for (int rp = 0; rp < RP; rp++) {
        float4 lo_l, hi_l, lo_r, hi_r;
        unpack2(accl[rp][0], lo_l.x, hi_l.x);
        unpack2(accl[rp][1], lo_l.y, hi_l.y);
        unpack2(accl[rp][2], lo_l.z, hi_l.z);
        unpack2(accl[rp][3], lo_l.w, hi_l.w);
        unpack2(accr[rp][0], lo_r.x, hi_r.x);
        unpack2(accr[rp][1], lo_r.y, hi_r.y);
        unpack2(accr[rp][2], lo_r.z, hi_r.z);
        unpack2(accr[rp][3], lo_r.w, hi_r.w);
        int gr0 = row0 + r0 + 2 * rp;
        int gr1 = gr0 + 1;
        if (gr0 < N_NODES) {
            *reinterpret_cast<float4*>(Yl + (size_t)gr0 * DOUT + c0) = lo_l;
            *reinterpret_cast<float4*>(Yr + (size_t)gr0 * DOUT + c0) = lo_r;
        }
        if (gr1 < N_NODES) {
            *reinterpret_cast<float4*>(Yl + (size_t)gr1 * DOUT + c0) = hi_l;
            *reinterpret_cast<float4*>(Yr + (size_t)gr1 * DOUT + c0) = hi_r;
        }
    }
}

// ---------------------------------------------------------------------------
// Fused gather + epilogue (128 ch): one warp per dst node.
// ---------------------------------------------------------------------------
template <bool RELU>
__global__ __launch_bounds__(256) void gather128_kernel(
    const float* __restrict__ yl, const float* __restrict__ yr,
    const float* __restrict__ b,
    const int* __restrict__ csr, const int* __restrict__ off,
    const int* __restrict__ cnt, float* __restrict__ out)
{
    int warp = (blockIdx.x * 256 + threadIdx.x) >> 5;
    int lane = threadIdx.x & 31;
    if (warp >= N_NODES) return;

    const int c = cnt[warp];
    const int o = off[warp];
    const float4* __restrict__ yl4 = reinterpret_cast<const float4*>(yl);

    float4 acc = make_float4(0.f, 0.f, 0.f, 0.f);
    int j = 0;
    for (; j + 4 <= c; j += 4) {
        int s0 = csr[o + j + 0];
        int s1 = csr[o + j + 1];
        int s2 = csr[o + j + 2];
        int s3 = csr[o + j + 3];
        float4 a0 = yl4[(size_t)s0 * 32 + lane];
        float4 a1 = yl4[(size_t)s1 * 32 + lane];
        float4 a2 = yl4[(size_t)s2 * 32 + lane];
        float4 a3 = yl4[(size_t)s3 * 32 + lane];
        acc.x += a0.x + a1.x + a2.x + a3.x;
        acc.y += a0.y + a1.y + a2.y + a3.y;
        acc.z += a0.z + a1.z + a2.z + a3.z;
        acc.w += a0.w + a1.w + a2.w + a3.w;
    }
    for (; j < c; j++) {
        int s = csr[o + j];
        float4 a = yl4[(size_t)s * 32 + lane];
        acc.x += a.x; acc.y += a.y; acc.z += a.z; acc.w += a.w;
    }

    float dinv = 1.0f / fmaxf((float)c, 1.0f);
    float4 r  = reinterpret_cast<const float4*>(yr)[(size_t)warp * 32 + lane];
    float4 bb = reinterpret_cast<const float4*>(b)[lane];
    float4 o4;
    o4.x = acc.x * dinv + r.x + bb.x;
    o4.y = acc.y * dinv + r.y + bb.y;
    o4.z = acc.z * dinv + r.z + bb.z;
    o4.w = acc.w * dinv + r.w + bb.w;
    if (RELU) {
        o4.x = fmaxf(o4.x, 0.f); o4.y = fmaxf(o4.y, 0.f);
        o4.z = fmaxf(o4.z, 0.f); o4.w = fmaxf(o4.w, 0.f);
    }
    reinterpret_cast<float4*>(out)[(size_t)warp * 32 + lane] = o4;
}

// 64-channel variant: one half-warp per node.
template <bool RELU>
__global__ __launch_bounds__(256) void gather64_kernel(
    const float* __restrict__ yl, const float* __restrict__ yr,
    const float* __restrict__ b,
    const int* __restrict__ csr, const int* __restrict__ off,
    const int* __restrict__ cnt, float* __restrict__ out)
{
    int node = (blockIdx.x * 256 + threadIdx.x) >> 4;
    int sub  = threadIdx.x & 15;
    if (node >= N_NODES) return;

    const int c = cnt[node];
    const int o = off[node];
    const float4* __restrict__ yl4 = reinterpret_cast<const float4*>(yl);

    float4 acc = make_float4(0.f, 0.f, 0.f, 0.f);
    int j = 0;
    for (; j + 4 <= c; j += 4) {
        int s0 = csr[o + j + 0];
        int s1 = csr[o + j + 1];
        int s2 = csr[o + j + 2];
        int s3 = csr[o + j + 3];
        float4 a0 = yl4[(size_t)s0 * 16 + sub];
        float4 a1 = yl4[(size_t)s1 * 16 + sub];
        float4 a2 = yl4[(size_t)s2 * 16 + sub];
        float4 a3 = yl4[(size_t)s3 * 16 + sub];
        acc.x += a0.x + a1.x + a2.x + a3.x;
        acc.y += a0.y + a1.y + a2.y + a3.y;
        acc.z += a0.z + a1.z + a2.z + a3.z;
        acc.w += a0.w + a1.w + a2.w + a3.w;
    }
    for (; j < c; j++) {
        int s = csr[o + j];
        float4 a = yl4[(size_t)s * 16 + sub];
        acc.x += a.x; acc.y += a.y; acc.z += a.z; acc.w += a.w;
    }

    float dinv = 1.0f / fmaxf((float)c, 1.0f);
    float4 r  = reinterpret_cast<const float4*>(yr)[(size_t)node * 16 + sub];
    float4 bb = reinterpret_cast<const float4*>(b)[sub];
    float4 o4;
    o4.x = acc.x * dinv + r.x + bb.x;
    o4.y = acc.y * dinv + r.y + bb.y;
    o4.z = acc.z * dinv + r.z + bb.z;
    o4.w = acc.w * dinv + r.w + bb.w;
    if (RELU) {
        o4.x = fmaxf(o4.x, 0.f); o4.y = fmaxf(o4.y, 0.f);
        o4.z = fmaxf(o4.z, 0.f); o4.w = fmaxf(o4.w, 0.f);
    }
    reinterpret_cast<float4*>(out)[(size_t)node * 16 + sub] = o4;
}

// ---------------------------------------------------------------------------
extern "C" void kernel_launch(void* const* d_in, const int* in_sizes, int n_in,
                              void* d_out, int out_size)
{
    const float* x   = (const float*)d_in[0];
    const void*  ei  = d_in[1];
    const float* Wl0 = (const float*)d_in[2];
    const float* Wr0 = (const float*)d_in[3];
    const float* b0  = (const float*)d_in[4];
    const float* Wl1 = (const float*)d_in[5];
    const float* Wr1 = (const float*)d_in[6];
    const float* b1  = (const float*)d_in[7];
    const float* Wl2 = (const float*)d_in[8];
    const float* Wr2 = (const float*)d_in[9];
    const float* b2  = (const float*)d_in[10];
    float* out = (float*)d_out;

    static float *p_yl = nullptr, *p_yr = nullptr, *p_A = nullptr, *p_B = nullptr;
    static int *p_cnt = nullptr, *p_off = nullptr, *p_cur = nullptr, *p_csr = nullptr, *p_bsum = nullptr;
    if (!p_yl) {
        cudaGetSymbolAddress((void**)&p_yl,   g_yl);
        cudaGetSymbolAddress((void**)&p_yr,   g_yr);
        cudaGetSymbolAddress((void**)&p_A,    g_bufA);
        cudaGetSymbolAddress((void**)&p_B,    g_bufB);
        cudaGetSymbolAddress((void**)&p_cnt,  g_cnt);
        cudaGetSymbolAddress((void**)&p_off,  g_off);
        cudaGetSymbolAddress((void**)&p_cur,  g_cur);
        cudaGetSymbolAddress((void**)&p_csr,  g_csr);
        cudaGetSymbolAddress((void**)&p_bsum, g_bsum);
    }

    const int NB_GEMM  = (N_NODES + 63) / 64;
    const int NB_SCAN  = (N_NODES + 1023) / 1024;
    const int NB_EDGE  = (N_EDGES + 255) / 256;
    const int NB_G128  = (N_NODES * 32 + 255) / 256;
    const int NB_G64   = (N_NODES * 16 + 255) / 256;

    // --- CSR build (recomputed every call: determinism) ---
    detect_kernel<<<1, 1>>>(ei);
    zero_int_kernel<<<(N_NODES + 255) / 256, 256>>>(p_cnt, N_NODES);
    hist_kernel<<<NB_EDGE, 256>>>(ei, p_cnt);
    blockreduce_kernel<<<NB_SCAN, 256>>>(p_cnt, p_bsum);
    scanpart_kernel<<<1, 32>>>(p_bsum, NB_SCAN);
    scanfinal_kernel<<<NB_SCAN, 256>>>(p_cnt, p_bsum, p_off, p_cur);
    fill_kernel<<<NB_EDGE, 256>>>(ei, p_cur, p_csr);

    // ---- Layer 0: x -> bufA (relu) ----
    gemm_dual_kernel<128><<<NB_GEMM, 256>>>(x, Wl0, Wr0, p_yl, p_yr);
    gather128_kernel<true><<<NB_G128, 256>>>(p_yl, p_yr, b0, p_csr, p_off, p_cnt, p_A);

    // ---- Layer 1: bufA -> bufB (relu) ----
    gemm_dual_kernel<128><<<NB_GEMM, 256>>>(p_A, Wl1, Wr1, p_yl, p_yr);
    gather128_kernel<true><<<NB_G128, 256>>>(p_yl, p_yr, b1, p_csr, p_off, p_cnt, p_B);

    // ---- Layer 2: bufB -> d_out (no relu, 64 ch) ----
    gemm_dual_kernel<64><<<NB_GEMM, 256>>>(p_B, Wl2, Wr2, p_yl, p_yr);
    gather64_kernel<false><<<NB_G64, 256>>>(p_yl, p_yr, b2, p_csr, p_off, p_cnt, out);
}

// round 6
// speedup vs baseline: 1.0381x; 1.0381x over previous
#include <cuda_runtime.h>
#include <cuda_bf16.h>
#include <cstdint>

// ---------------------------------------------------------------------------
// GraphSAGE 3-layer. Transform-then-aggregate + CSR gather.
// Critical-path overlap: gather_i (L2-bound, aux stream) runs concurrently
// with yr-GEMM_i (issue-bound, main stream). Epilogue of layers 0/1 is folded
// into the next layer's GEMM prologue; CSR build overlaps layer-0 GEMMs.
// ---------------------------------------------------------------------------

#define N_NODES 100000
#define N_EDGES 1600000

__device__ float g_yl[(size_t)N_NODES * 128];
__device__ float g_yr[(size_t)N_NODES * 128];
__device__ float g_bufA[(size_t)N_NODES * 128];   // agg L0 / agg L2
__device__ float g_bufB[(size_t)N_NODES * 128];   // agg L1
__device__ int   g_cnt[N_NODES];
__device__ int   g_off[N_NODES];
__device__ int   g_cur[N_NODES];
__device__ int   g_csr[N_EDGES];
__device__ int   g_bsum[128];
__device__ int   g_is64;

// --------------------------- edge dtype probe ------------------------------
__global__ void detect_kernel(const void* ei) {
    const long long* e64 = (const long long*)ei;
    int is64 = 1;
    for (int i = 0; i < 64; i++) {
        long long v = e64[i];
        if (v < 0 || v >= N_NODES) { is64 = 0; break; }
    }
    g_is64 = is64;
}

__device__ __forceinline__ int load_idx(const void* ei, long long pos) {
    if (g_is64) return (int)((const long long*)ei)[pos];
    return ((const int*)ei)[pos];
}

// ------------------------------- CSR build ---------------------------------
__global__ void zero_int_kernel(int* __restrict__ p, int n) {
    int i = blockIdx.x * blockDim.x + threadIdx.x;
    if (i < n) p[i] = 0;
}

__global__ void hist_kernel(const void* __restrict__ ei, int* __restrict__ cnt) {
    int e = blockIdx.x * blockDim.x + threadIdx.x;
    if (e < N_EDGES) {
        int d = load_idx(ei, (long long)N_EDGES + e);
        if ((unsigned)d < N_NODES) atomicAdd(&cnt[d], 1);
    }
}

__global__ void blockreduce_kernel(const int* __restrict__ cnt, int* __restrict__ bsum) {
    __shared__ int sm[256];
    int b = blockIdx.x, t = threadIdx.x;
    int base = b * 1024 + t * 4;
    int s = 0;
    #pragma unroll
    for (int i = 0; i < 4; i++) {
        int idx = base + i;
        if (idx < N_NODES) s += cnt[idx];
    }
    sm[t] = s; __syncthreads();
    for (int st = 128; st > 0; st >>= 1) {
        if (t < st) sm[t] += sm[t + st];
        __syncthreads();
    }
    if (t == 0) bsum[b] = sm[0];
}

__global__ void scanpart_kernel(int* __restrict__ bsum, int nb) {
    if (threadIdx.x == 0) {
        int acc = 0;
        for (int i = 0; i < nb; i++) { int v = bsum[i]; bsum[i] = acc; acc += v; }
    }
}

__global__ void scanfinal_kernel(const int* __restrict__ cnt, const int* __restrict__ bsum,
                                 int* __restrict__ off, int* __restrict__ cur) {
    __shared__ int sm[256];
    int b = blockIdx.x, t = threadIdx.x;
    int base = b * 1024 + t * 4;
    int v[4]; int s = 0;
    #pragma unroll
    for (int i = 0; i < 4; i++) {
        int idx = base + i;
        v[i] = (idx < N_NODES) ? cnt[idx] : 0;
        s += v[i];
    }
    sm[t] = s; __syncthreads();
    for (int st = 1; st < 256; st <<= 1) {
        int x = (t >= st) ? sm[t - st] : 0;
        __syncthreads();
        sm[t] += x;
        __syncthreads();
    }
    int run = sm[t] - s + bsum[b];
    #pragma unroll
    for (int i = 0; i < 4; i++) {
        int idx = base + i;
        if (idx < N_NODES) { off[idx] = run; cur[idx] = run; }
        run += v[i];
    }
}

__global__ void fill_kernel(const void* __restrict__ ei, int* __restrict__ cur,
                            int* __restrict__ csr) {
    int e = blockIdx.x * blockDim.x + threadIdx.x;
    if (e < N_EDGES) {
        int s = load_idx(ei, e);
        int d = load_idx(ei, (long long)N_EDGES + e);
        if ((unsigned)s < N_NODES && (unsigned)d < N_NODES) {
            int p = atomicAdd(&cur[d], 1);
            csr[p] = s;
        }
    }
}

// ---------------------------------------------------------------------------
// Single-output GEMM: Y[N,DOUT] = H @ W, where H is either X (PRO=false) or
// relu(agg/max(deg,1) + yrIn + bias) computed on the fly (PRO=true).
// 64 rows x DOUT cols per 256-thread block.
// ---------------------------------------------------------------------------
__device__ __forceinline__ void fma4(float4& acc, float s, const float4& wv) {
    acc.x += s * wv.x; acc.y += s * wv.y;
    acc.z += s * wv.z; acc.w += s * wv.w;
}

template <int DOUT, bool PRO>
__global__ __launch_bounds__(256) void gemm_one_kernel(
    const float* __restrict__ X,
    const float* __restrict__ agg, const float* __restrict__ yrIn,
    const int* __restrict__ cnt, const float* __restrict__ bias,
    const float* __restrict__ W, float* __restrict__ Y)
{
    constexpr int TR = 64;
    __shared__ float4 sx[TR][33];

    const int row0 = blockIdx.x * TR;
    const int t = threadIdx.x;

    #pragma unroll
    for (int i = t; i < TR * 32; i += 256) {
        int r = i >> 5, c4 = i & 31;
        int gr = row0 + r;
        float4 v = make_float4(0.f, 0.f, 0.f, 0.f);
        if (gr < N_NODES) {
            if (PRO) {
                float4 a  = reinterpret_cast<const float4*>(agg)[(size_t)gr * 32 + c4];
                float4 yv = reinterpret_cast<const float4*>(yrIn)[(size_t)gr * 32 + c4];
                float4 bb = reinterpret_cast<const float4*>(bias)[c4];
                float dinv = 1.0f / fmaxf((float)cnt[gr], 1.0f);
                v.x = fmaxf(a.x * dinv + yv.x + bb.x, 0.f);
                v.y = fmaxf(a.y * dinv + yv.y + bb.y, 0.f);
                v.z = fmaxf(a.z * dinv + yv.z + bb.z, 0.f);
                v.w = fmaxf(a.w * dinv + yv.w + bb.w, 0.f);
            } else {
                v = reinterpret_cast<const float4*>(X + (size_t)gr * 128)[c4];
            }
        }
        sx[r][c4] = v;
    }
    __syncthreads();

    constexpr int CG  = DOUT / 4;     // 32 or 16
    constexpr int NG  = 256 / CG;     // 8 or 16
    constexpr int RPT = TR / NG;      // 8 or 4
    const int cg = t % CG;
    const int rg = t / CG;
    const int c0 = cg * 4;
    const int r0 = rg * RPT;

    float4 acc[RPT];
    #pragma unroll
    for (int r = 0; r < RPT; r++) acc[r] = make_float4(0.f, 0.f, 0.f, 0.f);

    const float4* __restrict__ W4 = reinterpret_cast<const float4*>(W + c0);

    #pragma unroll 2
    for (int kq = 0; kq < 32; kq++) {
        float4 w0 = W4[(kq * 4 + 0) * CG];
        float4 w1 = W4[(kq * 4 + 1) * CG];
        float4 w2 = W4[(kq * 4 + 2) * CG];
        float4 w3 = W4[(kq * 4 + 3) * CG];
        #pragma unroll
        for (int r = 0; r < RPT; r++) {
            float4 xv = sx[r0 + r][kq];
            fma4(acc[r], xv.x, w0);
            fma4(acc[r], xv.y, w1);
            fma4(acc[r], xv.z, w2);
            fma4(acc[r], xv.w, w3);
        }
    }

    #pragma unroll
    for (int r = 0; r < RPT; r++) {
        int gr = row0 + r0 + r;
        if (gr < N_NODES)
            *reinterpret_cast<float4*>(Y + (size_t)gr * DOUT + c0) = acc[r];
    }
}

// ---------------------------------------------------------------------------
// Agg-only gathers: agg[n] = sum_{s in N(n)} yl[s]   (no epilogue)
// ---------------------------------------------------------------------------
__global__ __launch_bounds__(256) void gather128_agg_kernel(
    const float* __restrict__ yl,
    const int* __restrict__ csr, const int* __restrict__ off,
    const int* __restrict__ cnt, float* __restrict__ agg)
{
    int warp = (blockIdx.x * 256 + threadIdx.x) >> 5;
    int lane = threadIdx.x & 31;
    if (warp >= N_NODES) return;

    const int c = cnt[warp];
    const int o = off[warp];
    const float4* __restrict__ yl4 = reinterpret_cast<const float4*>(yl);

    float4 acc = make_float4(0.f, 0.f, 0.f, 0.f);
    int j = 0;
    for (; j + 4 <= c; j += 4) {
        int s0 = csr[o + j + 0];
        int s1 = csr[o + j + 1];
        int s2 = csr[o + j + 2];
        int s3 = csr[o + j + 3];
        float4 a0 = yl4[(size_t)s0 * 32 + lane];
        float4 a1 = yl4[(size_t)s1 * 32 + lane];
        float4 a2 = yl4[(size_t)s2 * 32 + lane];
        float4 a3 = yl4[(size_t)s3 * 32 + lane];
        acc.x += a0.x + a1.x + a2.x + a3.x;
        acc.y += a0.y + a1.y + a2.y + a3.y;
        acc.z += a0.z + a1.z + a2.z + a3.z;
        acc.w += a0.w + a1.w + a2.w + a3.w;
    }
    for (; j < c; j++) {
        int s = csr[o + j];
        float4 a = yl4[(size_t)s * 32 + lane];
        acc.x += a.x; acc.y += a.y; acc.z += a.z; acc.w += a.w;
    }
    reinterpret_cast<float4*>(agg)[(size_t)warp * 32 + lane] = acc;
}

__global__ __launch_bounds__(256) void gather64_agg_kernel(
    const float* __restrict__ yl,
    const int* __restrict__ csr, const int* __restrict__ off,
    const int* __restrict__ cnt, float* __restrict__ agg)
{
    int node = (blockIdx.x * 256 + threadIdx.x) >> 4;
    int sub  = threadIdx.x & 15;
    if (node >= N_NODES) return;

    const int c = cnt[node];
    const int o = off[node];
    const float4* __restrict__ yl4 = reinterpret_cast<const float4*>(yl);

    float4 acc = make_float4(0.f, 0.f, 0.f, 0.f);
    int j = 0;
    for (; j + 4 <= c; j += 4) {
        int s0 = csr[o + j + 0];
        int s1 = csr[o + j + 1];
        int s2 = csr[o + j + 2];
        int s3 = csr[o + j + 3];
        float4 a0 = yl4[(size_t)s0 * 16 + sub];
        float4 a1 = yl4[(size_t)s1 * 16 + sub];
        float4 a2 = yl4[(size_t)s2 * 16 + sub];
        float4 a3 = yl4[(size_t)s3 * 16 + sub];
        acc.x += a0.x + a1.x + a2.x + a3.x;
        acc.y += a0.y + a1.y + a2.y + a3.y;
        acc.z += a0.z + a1.z + a2.z + a3.z;
        acc.w += a0.w + a1.w + a2.w + a3.w;
    }
    for (; j < c; j++) {
        int s = csr[o + j];
        float4 a = yl4[(size_t)s * 16 + sub];
        acc.x += a.x; acc.y += a.y; acc.z += a.z; acc.w += a.w;
    }
    reinterpret_cast<float4*>(agg)[(size_t)node * 16 + sub] = acc;
}

// ---------------------------------------------------------------------------
// Final combine (64 ch, no relu): out = agg/max(deg,1) + yr + b
// ---------------------------------------------------------------------------
__global__ __launch_bounds__(256) void combine64_kernel(
    const float* __restrict__ agg, const float* __restrict__ yr,
    const float* __restrict__ b, const int* __restrict__ cnt,
    float* __restrict__ out)
{
    int i = blockIdx.x * blockDim.x + threadIdx.x;
    if (i >= N_NODES * 16) return;
    int node = i >> 4;
    int c4 = i & 15;

    float dinv = 1.0f / fmaxf((float)cnt[node], 1.0f);
    float4 a = reinterpret_cast<const float4*>(agg)[i];
    float4 r = reinterpret_cast<const float4*>(yr)[i];
    float4 bb = reinterpret_cast<const float4*>(b)[c4];

    float4 o;
    o.x = a.x * dinv + r.x + bb.x;
    o.y = a.y * dinv + r.y + bb.y;
    o.z = a.z * dinv + r.z + bb.z;
    o.w = a.w * dinv + r.w + bb.w;
    reinterpret_cast<float4*>(out)[i] = o;
}

// ---------------------------------------------------------------------------
extern "C" void kernel_launch(void* const* d_in, const int* in_sizes, int n_in,
                              void* d_out, int out_size)
{
    const float* x   = (const float*)d_in[0];
    const void*  ei  = d_in[1];
    const float* Wl0 = (const float*)d_in[2];
    const float* Wr0 = (const float*)d_in[3];
    const float* b0  = (const float*)d_in[4];
    const float* Wl1 = (const float*)d_in[5];
    const float* Wr1 = (const float*)d_in[6];
    const float* b1  = (const float*)d_in[7];
    const float* Wl2 = (const float*)d_in[8];
    const float* Wr2 = (const float*)d_in[9];
    const float* b2  = (const float*)d_in[10];
    float* out = (float*)d_out;

    static float *p_yl = nullptr, *p_yr = nullptr, *p_A = nullptr, *p_B = nullptr;
    static int *p_cnt = nullptr, *p_off = nullptr, *p_cur = nullptr, *p_csr = nullptr, *p_bsum = nullptr;
    static cudaStream_t s_aux = nullptr;
    static cudaEvent_t ev[8];
    if (!p_yl) {
        cudaGetSymbolAddress((void**)&p_yl,   g_yl);
        cudaGetSymbolAddress((void**)&p_yr,   g_yr);
        cudaGetSymbolAddress((void**)&p_A,    g_bufA);
        cudaGetSymbolAddress((void**)&p_B,    g_bufB);
        cudaGetSymbolAddress((void**)&p_cnt,  g_cnt);
        cudaGetSymbolAddress((void**)&p_off,  g_off);
        cudaGetSymbolAddress((void**)&p_cur,  g_cur);
        cudaGetSymbolAddress((void**)&p_csr,  g_csr);
        cudaGetSymbolAddress((void**)&p_bsum, g_bsum);
        cudaStreamCreateWithFlags(&s_aux, cudaStreamNonBlocking);
        for (int i = 0; i < 8; i++)
            cudaEventCreateWithFlags(&ev[i], cudaEventDisableTiming);
    }

    const int NB_GEMM  = (N_NODES + 63) / 64;
    const int NB_SCAN  = (N_NODES + 1023) / 1024;
    const int NB_EDGE  = (N_EDGES + 255) / 256;
    const int NB_G128  = (N_NODES * 32 + 255) / 256;
    const int NB_G64   = (N_NODES * 16 + 255) / 256;

    // Fork aux stream off the capture (main/default) stream.
    cudaEventRecord(ev[0], 0);
    cudaStreamWaitEvent(s_aux, ev[0], 0);

    // --- CSR build on aux (overlaps layer-0 GEMMs) ---
    detect_kernel<<<1, 1, 0, s_aux>>>(ei);
    zero_int_kernel<<<(N_NODES + 255) / 256, 256, 0, s_aux>>>(p_cnt, N_NODES);
    hist_kernel<<<NB_EDGE, 256, 0, s_aux>>>(ei, p_cnt);
    blockreduce_kernel<<<NB_SCAN, 256, 0, s_aux>>>(p_cnt, p_bsum);
    scanpart_kernel<<<1, 32, 0, s_aux>>>(p_bsum, NB_SCAN);
    scanfinal_kernel<<<NB_SCAN, 256, 0, s_aux>>>(p_cnt, p_bsum, p_off, p_cur);
    fill_kernel<<<NB_EDGE, 256, 0, s_aux>>>(ei, p_cur, p_csr);

    // ---- Layer 0 ----
    gemm_one_kernel<128, false><<<NB_GEMM, 256>>>(x, nullptr, nullptr, nullptr, nullptr, Wl0, p_yl);
    cudaEventRecord(ev[1], 0);
    cudaStreamWaitEvent(s_aux, ev[1], 0);
    gather128_agg_kernel<<<NB_G128, 256, 0, s_aux>>>(p_yl, p_csr, p_off, p_cnt, p_A);
    gemm_one_kernel<128, false><<<NB_GEMM, 256>>>(x, nullptr, nullptr, nullptr, nullptr, Wr0, p_yr);
    cudaEventRecord(ev[2], s_aux);
    cudaStreamWaitEvent(0, ev[2], 0);

    // ---- Layer 1 (h0 materialized on the fly from agg0/yr0/b0) ----
    gemm_one_kernel<128, true><<<NB_GEMM, 256>>>(nullptr, p_A, p_yr, p_cnt, b0, Wl1, p_yl);
    cudaEventRecord(ev[3], 0);
    cudaStreamWaitEvent(s_aux, ev[3], 0);
    gather128_agg_kernel<<<NB_G128, 256, 0, s_aux>>>(p_yl, p_csr, p_off, p_cnt, p_B);
    gemm_one_kernel<128, true><<<NB_GEMM, 256>>>(nullptr, p_A, p_yr, p_cnt, b0, Wr1, p_yr);
    cudaEventRecord(ev[4], s_aux);
    cudaStreamWaitEvent(0, ev[4], 0);

    // ---- Layer 2 (64 out; h1 from agg1/yr1/b1) ----
    gemm_one_kernel<64, true><<<NB_GEMM, 256>>>(nullptr, p_B, p_yr, p_cnt, b1, Wl2, p_yl);
    cudaEventRecord(ev[5], 0);
    cudaStreamWaitEvent(s_aux, ev[5], 0);
    gather64_agg_kernel<<<NB_G64, 256, 0, s_aux>>>(p_yl, p_csr, p_off, p_cnt, p_A);
    gemm_one_kernel<64, true><<<NB_GEMM, 256>>>(nullptr, p_B, p_yr, p_cnt, b1, Wr2, p_yr);
    cudaEventRecord(ev[6], s_aux);
    cudaStreamWaitEvent(0, ev[6], 0);

    combine64_kernel<<<NB_G64, 256>>>(p_A, p_yr, b2, p_cnt, out);
}